// round 4
// baseline (speedup 1.0000x reference)
#include <cuda_runtime.h>
#include <cuda_bf16.h>
#include <math.h>

// Problem constants
#define B_SZ   8192
#define D_IN   1024
#define E_EXP  8
#define T_TASK 4
#define H1_SZ  1024
#define H2_SZ  512
#define H3_SZ  256

// Scratch (device globals: allocation-free, graph-capture safe)
static __device__ float g_h1[(long)B_SZ * E_EXP * H1_SZ];     // 256 MB
static __device__ float g_h2[(long)B_SZ * E_EXP * H2_SZ];     // 128 MB
static __device__ float g_h3[(long)B_SZ * E_EXP * H3_SZ];     //  64 MB
static __device__ float g_gates[(long)B_SZ * E_EXP * T_TASK]; //   1 MB, layout [B][E][T]

// ---------------------------------------------------------------------------
// Generic batched SGEMM + bias + optional ReLU
// C[e][m][n] = act( sum_k A[e][m][k] * B[e][k][n] + bias[e][n] )
// Tiles: BM=128, BN=128, BK=16, 256 threads, 8x8 per-thread microtile,
// double-buffered shared memory.
// ---------------------------------------------------------------------------
#define BM 128
#define BN 128
#define BK 16
#define AS_PAD 4   // pad As rows to 132 floats (keeps float4 alignment, cuts store conflicts)

template <bool RELU>
__global__ __launch_bounds__(256, 2)
void sgemm_bias_relu(const float* __restrict__ A,
                     const float* __restrict__ Bm,
                     const float* __restrict__ bias,
                     float* __restrict__ C,
                     int K,
                     long lda, long ldb, long ldc,
                     long strideAe, long strideBe, long strideBiasE, long strideCe)
{
    const int tid = threadIdx.x;
    const int e   = blockIdx.z;

    A    += (long)e * strideAe;
    Bm   += (long)e * strideBe;
    bias += (long)e * strideBiasE;
    C    += (long)e * strideCe;

    const long mBase = (long)blockIdx.x * BM;
    const long nBase = (long)blockIdx.y * BN;

    __shared__ float As[2][BK][BM + AS_PAD];
    __shared__ float Bs[2][BK][BN];

    // Global load mapping
    const int aRow = tid >> 2;          // 0..63 (also +64)
    const int aCol = (tid & 3) << 2;    // 0,4,8,12 within BK
    const int bRow = tid >> 5;          // 0..7 (also +8)
    const int bCol = (tid & 31) << 2;   // 0..124

    // Compute mapping: 16x16 thread grid, 8x8 microtile each
    const int tx = tid & 15;
    const int ty = tid >> 4;
    const int m0 = ty << 3;
    const int n0 = tx << 3;

    const float* Ap0 = A + (mBase + aRow) * lda + aCol;
    const float* Ap1 = Ap0 + 64 * lda;
    const float* Bp0 = Bm + (long)bRow * ldb + nBase + bCol;
    const float* Bp1 = Bp0 + 8 * ldb;

    float acc[8][8];
    #pragma unroll
    for (int i = 0; i < 8; i++)
        #pragma unroll
        for (int j = 0; j < 8; j++) acc[i][j] = 0.0f;

    const int ntiles = K / BK;

    // Preload tile 0 into buffer 0
    {
        float4 a0 = *(const float4*)(Ap0);
        float4 a1 = *(const float4*)(Ap1);
        float4 b0 = *(const float4*)(Bp0);
        float4 b1 = *(const float4*)(Bp1);
        As[0][aCol + 0][aRow] = a0.x;  As[0][aCol + 1][aRow] = a0.y;
        As[0][aCol + 2][aRow] = a0.z;  As[0][aCol + 3][aRow] = a0.w;
        As[0][aCol + 0][aRow + 64] = a1.x;  As[0][aCol + 1][aRow + 64] = a1.y;
        As[0][aCol + 2][aRow + 64] = a1.z;  As[0][aCol + 3][aRow + 64] = a1.w;
        *(float4*)&Bs[0][bRow][bCol]     = b0;
        *(float4*)&Bs[0][bRow + 8][bCol] = b1;
    }
    __syncthreads();

    for (int kt = 0; kt < ntiles; kt++) {
        const int cur = kt & 1;
        float4 a0n, a1n, b0n, b1n;
        const bool has_next = (kt + 1 < ntiles);
        if (has_next) {
            const long ko = (long)(kt + 1) * BK;
            a0n = *(const float4*)(Ap0 + ko);
            a1n = *(const float4*)(Ap1 + ko);
            b0n = *(const float4*)(Bp0 + ko * ldb);
            b1n = *(const float4*)(Bp1 + ko * ldb);
        }

        #pragma unroll
        for (int k = 0; k < BK; k++) {
            float4 av0 = *(const float4*)&As[cur][k][m0];
            float4 av1 = *(const float4*)&As[cur][k][m0 + 4];
            float4 bv0 = *(const float4*)&Bs[cur][k][n0];
            float4 bv1 = *(const float4*)&Bs[cur][k][n0 + 4];
            float a[8] = {av0.x, av0.y, av0.z, av0.w, av1.x, av1.y, av1.z, av1.w};
            float b[8] = {bv0.x, bv0.y, bv0.z, bv0.w, bv1.x, bv1.y, bv1.z, bv1.w};
            #pragma unroll
            for (int i = 0; i < 8; i++)
                #pragma unroll
                for (int j = 0; j < 8; j++)
                    acc[i][j] = fmaf(a[i], b[j], acc[i][j]);
        }

        if (has_next) {
            const int nx = cur ^ 1;
            As[nx][aCol + 0][aRow] = a0n.x;  As[nx][aCol + 1][aRow] = a0n.y;
            As[nx][aCol + 2][aRow] = a0n.z;  As[nx][aCol + 3][aRow] = a0n.w;
            As[nx][aCol + 0][aRow + 64] = a1n.x;  As[nx][aCol + 1][aRow + 64] = a1n.y;
            As[nx][aCol + 2][aRow + 64] = a1n.z;  As[nx][aCol + 3][aRow + 64] = a1n.w;
            *(float4*)&Bs[nx][bRow][bCol]     = b0n;
            *(float4*)&Bs[nx][bRow + 8][bCol] = b1n;
            __syncthreads();
        }
    }

    // Epilogue: bias + relu + store (vectorized bias load)
    float4 bv0 = *(const float4*)(bias + nBase + n0);
    float4 bv1 = *(const float4*)(bias + nBase + n0 + 4);
    const float bj[8] = {bv0.x, bv0.y, bv0.z, bv0.w, bv1.x, bv1.y, bv1.z, bv1.w};

    #pragma unroll
    for (int i = 0; i < 8; i++) {
        float* cp = C + (mBase + m0 + i) * ldc + nBase + n0;
        float4 r0, r1;
        r0.x = acc[i][0] + bj[0];  r0.y = acc[i][1] + bj[1];
        r0.z = acc[i][2] + bj[2];  r0.w = acc[i][3] + bj[3];
        r1.x = acc[i][4] + bj[4];  r1.y = acc[i][5] + bj[5];
        r1.z = acc[i][6] + bj[6];  r1.w = acc[i][7] + bj[7];
        if (RELU) {
            r0.x = fmaxf(r0.x, 0.0f); r0.y = fmaxf(r0.y, 0.0f);
            r0.z = fmaxf(r0.z, 0.0f); r0.w = fmaxf(r0.w, 0.0f);
            r1.x = fmaxf(r1.x, 0.0f); r1.y = fmaxf(r1.y, 0.0f);
            r1.z = fmaxf(r1.z, 0.0f); r1.w = fmaxf(r1.w, 0.0f);
        }
        *(float4*)(cp)     = r0;
        *(float4*)(cp + 4) = r1;
    }
}

// ---------------------------------------------------------------------------
// Gate kernel: logits = x @ gate_w  (K=1024, 32 outs), softmax over experts
// within each task group of 8; store gates as [B][E][T].
// One block = 8 batch rows, 256 threads: thread (r = tid/32, c = tid%32).
// ---------------------------------------------------------------------------
__global__ __launch_bounds__(256)
void gate_kernel(const float* __restrict__ x,
                 const float* __restrict__ gw,
                 float* __restrict__ gates)
{
    __shared__ float xs[8][D_IN];     // 32 KB
    __shared__ float gws[64][32];     // 8 KB chunk of gate_w
    __shared__ float lg[8][32];       // logits

    const int tid = threadIdx.x;
    const long b0 = (long)blockIdx.x * 8;

    // load 8 rows of x
    {
        const float4* xg  = (const float4*)(x + b0 * D_IN);
        float4*       xs4 = (float4*)xs;
        #pragma unroll
        for (int i = tid; i < 8 * D_IN / 4; i += 256) xs4[i] = xg[i];
    }

    const int r = tid >> 5;   // 0..7  batch row within block
    const int c = tid & 31;   // 0..31 logit index (= t*8 + e)

    float acc = 0.0f;
    for (int kc = 0; kc < D_IN; kc += 64) {
        __syncthreads();
        const float4* gwg = (const float4*)(gw + (long)kc * 32);
        float4*       gs4 = (float4*)gws;
        for (int i = tid; i < 64 * 32 / 4; i += 256) gs4[i] = gwg[i];
        __syncthreads();
        #pragma unroll
        for (int k = 0; k < 64; k++)
            acc = fmaf(xs[r][kc + k], gws[k][c], acc);
    }

    lg[r][c] = acc;
    __syncthreads();

    // softmax over the 8 experts of this (r, t) group
    const int t  = c >> 3;
    const int eI = c & 7;
    const int base = t << 3;
    float mx = -1e30f;
    #pragma unroll
    for (int j = 0; j < 8; j++) mx = fmaxf(mx, lg[r][base + j]);
    float s = 0.0f;
    #pragma unroll
    for (int j = 0; j < 8; j++) s += expf(lg[r][base + j] - mx);
    float gate = expf(acc - mx) / s;

    // gates layout [B][E][T]
    gates[(b0 + r) * (E_EXP * T_TASK) + eI * T_TASK + t] = gate;
}

// ---------------------------------------------------------------------------
// Combine: out[t][b][d] = sum_e h3[b][e][d] * gates[b][e][t]
// One block = 2 batch rows, 128 threads; each thread owns 4 d's via float4.
// ---------------------------------------------------------------------------
__global__ __launch_bounds__(128)
void combine_kernel(const float* __restrict__ h3,
                    const float* __restrict__ gates,
                    float* __restrict__ out)
{
    const int  tid = threadIdx.x;
    const long b   = (long)blockIdx.x * 2 + (tid >> 6); // 64 threads per row
    const int  d4  = (tid & 63);                        // float4 index (0..63)

    __shared__ float g[2][E_EXP * T_TASK];
    if (tid < 2 * E_EXP * T_TASK)
        g[tid >> 5][tid & 31] =
            gates[((long)blockIdx.x * 2 + (tid >> 5)) * (E_EXP * T_TASK) + (tid & 31)];
    __syncthreads();

    const int rsel = tid >> 6;
    float4 a0 = {0,0,0,0}, a1 = {0,0,0,0}, a2 = {0,0,0,0}, a3 = {0,0,0,0};
    #pragma unroll
    for (int e = 0; e < E_EXP; e++) {
        float4 v = *(const float4*)(h3 + ((b * E_EXP + e) * H3_SZ) + d4 * 4);
        const float g0 = g[rsel][e * T_TASK + 0];
        const float g1 = g[rsel][e * T_TASK + 1];
        const float g2 = g[rsel][e * T_TASK + 2];
        const float g3 = g[rsel][e * T_TASK + 3];
        a0.x = fmaf(v.x, g0, a0.x); a0.y = fmaf(v.y, g0, a0.y);
        a0.z = fmaf(v.z, g0, a0.z); a0.w = fmaf(v.w, g0, a0.w);
        a1.x = fmaf(v.x, g1, a1.x); a1.y = fmaf(v.y, g1, a1.y);
        a1.z = fmaf(v.z, g1, a1.z); a1.w = fmaf(v.w, g1, a1.w);
        a2.x = fmaf(v.x, g2, a2.x); a2.y = fmaf(v.y, g2, a2.y);
        a2.z = fmaf(v.z, g2, a2.z); a2.w = fmaf(v.w, g2, a2.w);
        a3.x = fmaf(v.x, g3, a3.x); a3.y = fmaf(v.y, g3, a3.y);
        a3.z = fmaf(v.z, g3, a3.z); a3.w = fmaf(v.w, g3, a3.w);
    }
    const long base = b * H3_SZ + d4 * 4;
    const long ts   = (long)B_SZ * H3_SZ;
    *(float4*)(out + 0 * ts + base) = a0;
    *(float4*)(out + 1 * ts + base) = a1;
    *(float4*)(out + 2 * ts + base) = a2;
    *(float4*)(out + 3 * ts + base) = a3;
}

// ---------------------------------------------------------------------------
extern "C" void kernel_launch(void* const* d_in, const int* in_sizes, int n_in,
                              void* d_out, int out_size)
{
    const float* x      = (const float*)d_in[0];
    const float* W1     = (const float*)d_in[1];
    const float* b1     = (const float*)d_in[2];
    const float* W2     = (const float*)d_in[3];
    const float* b2     = (const float*)d_in[4];
    const float* W3     = (const float*)d_in[5];
    const float* b3     = (const float*)d_in[6];
    const float* gate_w = (const float*)d_in[7];
    float* out = (float*)d_out;

    float *h1, *h2, *h3, *gates;
    cudaGetSymbolAddress((void**)&h1, g_h1);
    cudaGetSymbolAddress((void**)&h2, g_h2);
    cudaGetSymbolAddress((void**)&h3, g_h3);
    cudaGetSymbolAddress((void**)&gates, g_gates);

    // Gates
    gate_kernel<<<B_SZ / 8, 256>>>(x, gate_w, gates);

    // Layer 1: h1[b][e][:] = relu(x[b,:] @ W1[e] + b1[e])
    {
        dim3 grid(B_SZ / BM, H1_SZ / BN, E_EXP);
        sgemm_bias_relu<true><<<grid, 256>>>(
            x, W1, b1, h1, D_IN,
            /*lda*/ D_IN, /*ldb*/ H1_SZ, /*ldc*/ (long)E_EXP * H1_SZ,
            /*strideAe*/ 0, /*strideBe*/ (long)D_IN * H1_SZ,
            /*strideBiasE*/ H1_SZ, /*strideCe*/ H1_SZ);
    }

    // Layer 2: h2 = relu(h1 @ W2 + b2)
    {
        dim3 grid(B_SZ / BM, H2_SZ / BN, E_EXP);
        sgemm_bias_relu<true><<<grid, 256>>>(
            h1, W2, b2, h2, H1_SZ,
            /*lda*/ (long)E_EXP * H1_SZ, /*ldb*/ H2_SZ, /*ldc*/ (long)E_EXP * H2_SZ,
            /*strideAe*/ H1_SZ, /*strideBe*/ (long)H1_SZ * H2_SZ,
            /*strideBiasE*/ H2_SZ, /*strideCe*/ H2_SZ);
    }

    // Layer 3: h3 = relu(h2 @ W3 + b3)
    {
        dim3 grid(B_SZ / BM, H3_SZ / BN, E_EXP);
        sgemm_bias_relu<true><<<grid, 256>>>(
            h2, W3, b3, h3, H2_SZ,
            /*lda*/ (long)E_EXP * H2_SZ, /*ldb*/ H3_SZ, /*ldc*/ (long)E_EXP * H3_SZ,
            /*strideAe*/ H2_SZ, /*strideBe*/ (long)H2_SZ * H3_SZ,
            /*strideBiasE*/ H3_SZ, /*strideCe*/ H3_SZ);
    }

    // Combine with gates
    combine_kernel<<<B_SZ / 2, 128>>>(h3, gates, out);
}

// round 5
// speedup vs baseline: 2.7376x; 2.7376x over previous
#include <cuda_runtime.h>
#include <cuda_bf16.h>
#include <math.h>
#include <stdint.h>

// Problem constants
#define B_SZ   8192
#define D_IN   1024
#define E_EXP  8
#define T_TASK 4
#define H1_SZ  1024
#define H2_SZ  512
#define H3_SZ  256

// Scratch (device globals: allocation-free, graph-capture safe)
static __device__ float g_h1[(long)B_SZ * E_EXP * H1_SZ];     // 256 MB
static __device__ float g_h2[(long)B_SZ * E_EXP * H2_SZ];     // 128 MB
static __device__ float g_h3[(long)B_SZ * E_EXP * H3_SZ];     //  64 MB
static __device__ float g_gates[(long)B_SZ * E_EXP * T_TASK]; //   1 MB, layout [B][E][T]

__device__ __forceinline__ unsigned f2tf32(float x) {
    unsigned r;
    asm("cvt.rna.tf32.f32 %0, %1;" : "=r"(r) : "f"(x));
    return r;
}

// ---------------------------------------------------------------------------
// Batched TF32 tensor-core GEMM + bias + ReLU
// C[e][m][n] = relu( sum_k A[e][m][k] * B[e][k][n] + bias[e][n] )
// BM=128, BN=128, BK=16, 256 threads (8 warps, 2x4), warp tile 64x32.
// mma.sync.aligned.m16n8k8 tf32, fp32 accumulate.
// As[m][k] stride 20  -> fragment loads conflict-free (20*qr+qc distinct mod 32)
// Bs[k][n] stride 136 -> fragment loads conflict-free (8*qc+qr distinct mod 32)
// ---------------------------------------------------------------------------
#define BM 128
#define BN 128
#define BK 16
#define AP 20    // As row stride in words
#define BP 136   // Bs row stride in words

template <bool RELU>
__global__ __launch_bounds__(256, 2)
void tgemm_bias_relu(const float* __restrict__ A,
                     const float* __restrict__ Bm,
                     const float* __restrict__ bias,
                     float* __restrict__ C,
                     int K,
                     long lda, long ldb, long ldc,
                     long strideAe, long strideBe, long strideBiasE, long strideCe)
{
    const int tid = threadIdx.x;
    const int e   = blockIdx.z;

    A    += (long)e * strideAe;
    Bm   += (long)e * strideBe;
    bias += (long)e * strideBiasE;
    C    += (long)e * strideCe;

    const long mBase = (long)blockIdx.x * BM;
    const long nBase = (long)blockIdx.y * BN;

    __shared__ uint32_t As[2][BM][AP];   // [m][k]  2*128*20*4  = 20480 B
    __shared__ uint32_t Bs[2][BK][BP];   // [k][n]  2*16*136*4  = 17408 B

    // ---- global load mapping (same proven scheme as baseline) ----
    const int aRow = tid >> 2;          // 0..63 (also +64): m within tile
    const int aCol = (tid & 3) << 2;    // 0,4,8,12: k within BK
    const int bRow = tid >> 5;          // 0..7 (also +8): k within BK
    const int bCol = (tid & 31) << 2;   // 0..124: n within BN

    // ---- warp/lane mapping for mma ----
    const int w    = tid >> 5;
    const int wm   = w & 1;             // 2 warps in M
    const int wn   = w >> 1;            // 4 warps in N
    const int lane = tid & 31;
    const int qr   = lane >> 2;         // 0..7
    const int qc   = lane & 3;          // 0..3

    const float* Ap0 = A + (mBase + aRow) * lda + aCol;
    const float* Ap1 = Ap0 + 64 * lda;
    const float* Bp0 = Bm + (long)bRow * ldb + nBase + bCol;
    const float* Bp1 = Bp0 + 8 * ldb;

    float acc[4][4][4];
    #pragma unroll
    for (int i = 0; i < 4; i++)
        #pragma unroll
        for (int j = 0; j < 4; j++)
            #pragma unroll
            for (int r = 0; r < 4; r++) acc[i][j][r] = 0.0f;

    const int ntiles = K / BK;

    // ---- stage tile 0 into buffer 0 ----
    {
        float4 a0 = *(const float4*)(Ap0);
        float4 a1 = *(const float4*)(Ap1);
        float4 b0 = *(const float4*)(Bp0);
        float4 b1 = *(const float4*)(Bp1);
        // A: direct copy (m-major), cvt to tf32
        As[0][aRow][aCol + 0]      = f2tf32(a0.x);
        As[0][aRow][aCol + 1]      = f2tf32(a0.y);
        As[0][aRow][aCol + 2]      = f2tf32(a0.z);
        As[0][aRow][aCol + 3]      = f2tf32(a0.w);
        As[0][aRow + 64][aCol + 0] = f2tf32(a1.x);
        As[0][aRow + 64][aCol + 1] = f2tf32(a1.y);
        As[0][aRow + 64][aCol + 2] = f2tf32(a1.z);
        As[0][aRow + 64][aCol + 3] = f2tf32(a1.w);
        uint4 bu0 = { f2tf32(b0.x), f2tf32(b0.y), f2tf32(b0.z), f2tf32(b0.w) };
        uint4 bu1 = { f2tf32(b1.x), f2tf32(b1.y), f2tf32(b1.z), f2tf32(b1.w) };
        *(uint4*)&Bs[0][bRow][bCol]     = bu0;
        *(uint4*)&Bs[0][bRow + 8][bCol] = bu1;
    }
    __syncthreads();

    for (int kt = 0; kt < ntiles; kt++) {
        const int cur = kt & 1;
        float4 a0n, a1n, b0n, b1n;
        const bool has_next = (kt + 1 < ntiles);
        if (has_next) {
            const long ko = (long)(kt + 1) * BK;
            a0n = *(const float4*)(Ap0 + ko);
            a1n = *(const float4*)(Ap1 + ko);
            b0n = *(const float4*)(Bp0 + ko * ldb);
            b1n = *(const float4*)(Bp1 + ko * ldb);
        }

        // ---- compute: two k8 steps ----
        #pragma unroll
        for (int ks = 0; ks < BK; ks += 8) {
            uint32_t aF[4][4];
            uint32_t bF[4][2];
            #pragma unroll
            for (int i = 0; i < 4; i++) {
                const int mtb = wm * 64 + i * 16;
                aF[i][0] = As[cur][mtb + qr]    [ks + qc];
                aF[i][1] = As[cur][mtb + qr + 8][ks + qc];
                aF[i][2] = As[cur][mtb + qr]    [ks + qc + 4];
                aF[i][3] = As[cur][mtb + qr + 8][ks + qc + 4];
            }
            #pragma unroll
            for (int j = 0; j < 4; j++) {
                const int ntb = wn * 32 + j * 8;
                bF[j][0] = Bs[cur][ks + qc]    [ntb + qr];
                bF[j][1] = Bs[cur][ks + qc + 4][ntb + qr];
            }
            #pragma unroll
            for (int i = 0; i < 4; i++)
                #pragma unroll
                for (int j = 0; j < 4; j++) {
                    asm volatile(
                        "mma.sync.aligned.m16n8k8.row.col.f32.tf32.tf32.f32 "
                        "{%0,%1,%2,%3}, {%4,%5,%6,%7}, {%8,%9}, {%0,%1,%2,%3};\n"
                        : "+f"(acc[i][j][0]), "+f"(acc[i][j][1]),
                          "+f"(acc[i][j][2]), "+f"(acc[i][j][3])
                        : "r"(aF[i][0]), "r"(aF[i][1]), "r"(aF[i][2]), "r"(aF[i][3]),
                          "r"(bF[j][0]), "r"(bF[j][1]));
                }
        }

        if (has_next) {
            const int nx = cur ^ 1;
            As[nx][aRow][aCol + 0]      = f2tf32(a0n.x);
            As[nx][aRow][aCol + 1]      = f2tf32(a0n.y);
            As[nx][aRow][aCol + 2]      = f2tf32(a0n.z);
            As[nx][aRow][aCol + 3]      = f2tf32(a0n.w);
            As[nx][aRow + 64][aCol + 0] = f2tf32(a1n.x);
            As[nx][aRow + 64][aCol + 1] = f2tf32(a1n.y);
            As[nx][aRow + 64][aCol + 2] = f2tf32(a1n.z);
            As[nx][aRow + 64][aCol + 3] = f2tf32(a1n.w);
            uint4 bu0 = { f2tf32(b0n.x), f2tf32(b0n.y), f2tf32(b0n.z), f2tf32(b0n.w) };
            uint4 bu1 = { f2tf32(b1n.x), f2tf32(b1n.y), f2tf32(b1n.z), f2tf32(b1n.w) };
            *(uint4*)&Bs[nx][bRow][bCol]     = bu0;
            *(uint4*)&Bs[nx][bRow + 8][bCol] = bu1;
            __syncthreads();
        }
    }

    // ---- epilogue: bias + relu + store ----
    // C fragment: c0:(qr, 2qc) c1:(qr, 2qc+1) c2:(qr+8, 2qc) c3:(qr+8, 2qc+1)
    #pragma unroll
    for (int j = 0; j < 4; j++) {
        const int ncol = wn * 32 + j * 8 + 2 * qc;
        const float2 bj = *(const float2*)(bias + nBase + ncol);
        #pragma unroll
        for (int i = 0; i < 4; i++) {
            const long r0 = mBase + wm * 64 + i * 16 + qr;
            float2 v0, v1;
            v0.x = acc[i][j][0] + bj.x;  v0.y = acc[i][j][1] + bj.y;
            v1.x = acc[i][j][2] + bj.x;  v1.y = acc[i][j][3] + bj.y;
            if (RELU) {
                v0.x = fmaxf(v0.x, 0.0f); v0.y = fmaxf(v0.y, 0.0f);
                v1.x = fmaxf(v1.x, 0.0f); v1.y = fmaxf(v1.y, 0.0f);
            }
            *(float2*)(C + r0 * ldc + nBase + ncol)       = v0;
            *(float2*)(C + (r0 + 8) * ldc + nBase + ncol) = v1;
        }
    }
}

// ---------------------------------------------------------------------------
// Gate kernel: logits = x @ gate_w (K=1024, 32 outs), softmax over experts
// within each task group of 8; store gates as [B][E][T]. (fp32, exact)
// ---------------------------------------------------------------------------
__global__ __launch_bounds__(256)
void gate_kernel(const float* __restrict__ x,
                 const float* __restrict__ gw,
                 float* __restrict__ gates)
{
    __shared__ float xs[8][D_IN];     // 32 KB
    __shared__ float gws[64][32];     // 8 KB chunk of gate_w
    __shared__ float lg[8][32];       // logits

    const int tid = threadIdx.x;
    const long b0 = (long)blockIdx.x * 8;

    {
        const float4* xg  = (const float4*)(x + b0 * D_IN);
        float4*       xs4 = (float4*)xs;
        #pragma unroll
        for (int i = tid; i < 8 * D_IN / 4; i += 256) xs4[i] = xg[i];
    }

    const int r = tid >> 5;
    const int c = tid & 31;

    float acc = 0.0f;
    for (int kc = 0; kc < D_IN; kc += 64) {
        __syncthreads();
        const float4* gwg = (const float4*)(gw + (long)kc * 32);
        float4*       gs4 = (float4*)gws;
        for (int i = tid; i < 64 * 32 / 4; i += 256) gs4[i] = gwg[i];
        __syncthreads();
        #pragma unroll
        for (int k = 0; k < 64; k++)
            acc = fmaf(xs[r][kc + k], gws[k][c], acc);
    }

    lg[r][c] = acc;
    __syncthreads();

    const int t  = c >> 3;
    const int eI = c & 7;
    const int base = t << 3;
    float mx = -1e30f;
    #pragma unroll
    for (int j = 0; j < 8; j++) mx = fmaxf(mx, lg[r][base + j]);
    float s = 0.0f;
    #pragma unroll
    for (int j = 0; j < 8; j++) s += expf(lg[r][base + j] - mx);
    float gate = expf(acc - mx) / s;

    gates[(b0 + r) * (E_EXP * T_TASK) + eI * T_TASK + t] = gate;
}

// ---------------------------------------------------------------------------
// Combine: out[t][b][d] = sum_e h3[b][e][d] * gates[b][e][t]
// One block = 2 batch rows, 128 threads; each thread owns 4 d's via float4.
// ---------------------------------------------------------------------------
__global__ __launch_bounds__(128)
void combine_kernel(const float* __restrict__ h3,
                    const float* __restrict__ gates,
                    float* __restrict__ out)
{
    const int  tid = threadIdx.x;
    const long b   = (long)blockIdx.x * 2 + (tid >> 6);
    const int  d4  = (tid & 63);

    __shared__ float g[2][E_EXP * T_TASK];
    if (tid < 2 * E_EXP * T_TASK)
        g[tid >> 5][tid & 31] =
            gates[((long)blockIdx.x * 2 + (tid >> 5)) * (E_EXP * T_TASK) + (tid & 31)];
    __syncthreads();

    const int rsel = tid >> 6;
    float4 a0 = {0,0,0,0}, a1 = {0,0,0,0}, a2 = {0,0,0,0}, a3 = {0,0,0,0};
    #pragma unroll
    for (int e = 0; e < E_EXP; e++) {
        float4 v = *(const float4*)(h3 + ((b * E_EXP + e) * H3_SZ) + d4 * 4);
        const float g0 = g[rsel][e * T_TASK + 0];
        const float g1 = g[rsel][e * T_TASK + 1];
        const float g2 = g[rsel][e * T_TASK + 2];
        const float g3 = g[rsel][e * T_TASK + 3];
        a0.x = fmaf(v.x, g0, a0.x); a0.y = fmaf(v.y, g0, a0.y);
        a0.z = fmaf(v.z, g0, a0.z); a0.w = fmaf(v.w, g0, a0.w);
        a1.x = fmaf(v.x, g1, a1.x); a1.y = fmaf(v.y, g1, a1.y);
        a1.z = fmaf(v.z, g1, a1.z); a1.w = fmaf(v.w, g1, a1.w);
        a2.x = fmaf(v.x, g2, a2.x); a2.y = fmaf(v.y, g2, a2.y);
        a2.z = fmaf(v.z, g2, a2.z); a2.w = fmaf(v.w, g2, a2.w);
        a3.x = fmaf(v.x, g3, a3.x); a3.y = fmaf(v.y, g3, a3.y);
        a3.z = fmaf(v.z, g3, a3.z); a3.w = fmaf(v.w, g3, a3.w);
    }
    const long base = b * H3_SZ + d4 * 4;
    const long ts   = (long)B_SZ * H3_SZ;
    *(float4*)(out + 0 * ts + base) = a0;
    *(float4*)(out + 1 * ts + base) = a1;
    *(float4*)(out + 2 * ts + base) = a2;
    *(float4*)(out + 3 * ts + base) = a3;
}

// ---------------------------------------------------------------------------
extern "C" void kernel_launch(void* const* d_in, const int* in_sizes, int n_in,
                              void* d_out, int out_size)
{
    const float* x      = (const float*)d_in[0];
    const float* W1     = (const float*)d_in[1];
    const float* b1     = (const float*)d_in[2];
    const float* W2     = (const float*)d_in[3];
    const float* b2     = (const float*)d_in[4];
    const float* W3     = (const float*)d_in[5];
    const float* b3     = (const float*)d_in[6];
    const float* gate_w = (const float*)d_in[7];
    float* out = (float*)d_out;

    float *h1, *h2, *h3, *gates;
    cudaGetSymbolAddress((void**)&h1, g_h1);
    cudaGetSymbolAddress((void**)&h2, g_h2);
    cudaGetSymbolAddress((void**)&h3, g_h3);
    cudaGetSymbolAddress((void**)&gates, g_gates);

    // Gates (fp32)
    gate_kernel<<<B_SZ / 8, 256>>>(x, gate_w, gates);

    // Layer 1: h1 = relu(x @ W1[e] + b1[e])
    {
        dim3 grid(B_SZ / BM, H1_SZ / BN, E_EXP);
        tgemm_bias_relu<true><<<grid, 256>>>(
            x, W1, b1, h1, D_IN,
            /*lda*/ D_IN, /*ldb*/ H1_SZ, /*ldc*/ (long)E_EXP * H1_SZ,
            /*strideAe*/ 0, /*strideBe*/ (long)D_IN * H1_SZ,
            /*strideBiasE*/ H1_SZ, /*strideCe*/ H1_SZ);
    }

    // Layer 2: h2 = relu(h1 @ W2 + b2)
    {
        dim3 grid(B_SZ / BM, H2_SZ / BN, E_EXP);
        tgemm_bias_relu<true><<<grid, 256>>>(
            h1, W2, b2, h2, H1_SZ,
            /*lda*/ (long)E_EXP * H1_SZ, /*ldb*/ H2_SZ, /*ldc*/ (long)E_EXP * H2_SZ,
            /*strideAe*/ H1_SZ, /*strideBe*/ (long)H1_SZ * H2_SZ,
            /*strideBiasE*/ H2_SZ, /*strideCe*/ H2_SZ);
    }

    // Layer 3: h3 = relu(h2 @ W3 + b3)
    {
        dim3 grid(B_SZ / BM, H3_SZ / BN, E_EXP);
        tgemm_bias_relu<true><<<grid, 256>>>(
            h2, W3, b3, h3, H2_SZ,
            /*lda*/ (long)E_EXP * H2_SZ, /*ldb*/ H3_SZ, /*ldc*/ (long)E_EXP * H3_SZ,
            /*strideAe*/ H2_SZ, /*strideBe*/ (long)H2_SZ * H3_SZ,
            /*strideBiasE*/ H3_SZ, /*strideCe*/ H3_SZ);
    }

    // Combine with gates
    combine_kernel<<<B_SZ / 2, 128>>>(h3, gates, out);
}

// round 9
// speedup vs baseline: 3.1931x; 1.1664x over previous
#include <cuda_runtime.h>
#include <cuda_bf16.h>
#include <math.h>
#include <stdint.h>

// Problem constants
#define B_SZ   8192
#define D_IN   1024
#define E_EXP  8
#define T_TASK 4
#define H1_SZ  1024
#define H2_SZ  512
#define H3_SZ  256

// Scratch (device globals: allocation-free, graph-capture safe)
static __device__ float g_h1[(long)B_SZ * E_EXP * H1_SZ];       // 256 MB
static __device__ float g_h2[(long)B_SZ * E_EXP * H2_SZ];       // 128 MB
static __device__ float g_h3[(long)B_SZ * E_EXP * H3_SZ];       //  64 MB
static __device__ float g_gates[(long)B_SZ * E_EXP * T_TASK];   //   1 MB
static __device__ float g_xr [(long)B_SZ * D_IN];               //  32 MB  x  (tf32-rounded)
static __device__ float g_w1r[(long)E_EXP * D_IN * H1_SZ];      //  32 MB  W1 (tf32-rounded)
static __device__ float g_w2r[(long)E_EXP * H1_SZ * H2_SZ];     //  16 MB  W2 (tf32-rounded)
static __device__ float g_w3r[(long)E_EXP * H2_SZ * H3_SZ];     //   4 MB  W3 (tf32-rounded)

__device__ __forceinline__ float rna_tf32(float x) {
    uint32_t r;
    asm("cvt.rna.tf32.f32 %0, %1;" : "=r"(r) : "f"(x));
    return __uint_as_float(r);
}

__device__ __forceinline__ uint32_t smem_u32(const void* p) {
    uint32_t a;
    asm("{ .reg .u64 t; cvta.to.shared.u64 t, %1; cvt.u32.u64 %0, t; }" : "=r"(a) : "l"(p));
    return a;
}

__device__ __forceinline__ void cp_async16(uint32_t dst, const void* src) {
    asm volatile("cp.async.cg.shared.global [%0], [%1], 16;"
                 :: "r"(dst), "l"(src) : "memory");
}
#define CP_COMMIT()  asm volatile("cp.async.commit_group;" ::: "memory")
#define CP_WAIT(n)   asm volatile("cp.async.wait_group %0;" :: "n"(n) : "memory")

// ---------------------------------------------------------------------------
// TF32 mma.sync GEMM: C[e][m][n] = act( sum_k A[e][m][k]*B[e][k][n] + bias[e][n] )
// Block tile 128(M) x 256(N), BK=16, 256 threads = 8 warps (2x4), warp 64x64.
// 3-stage cp.async.cg pipeline (L1-bypass staging). All operands must be
// tf32-exact in GMEM (raw-byte staging).
// Smem: As[m][20] (conflict-free frags: (20*qr+qc)%32 distinct)
//       Bs[k][264] (264%32==8 -> (8*qc+qr)%32 distinct)
// ---------------------------------------------------------------------------
#define BK     16
#define AP     20           // As row stride (words)
#define BP     264          // Bs row stride (words)
#define A_STG  (128 * AP * 4)       // 10240 B per stage
#define B_STG  (BK * BP * 4)        // 16896 B per stage
#define SA_OFF(s)  ((s) * A_STG)
#define SB_OFF(s)  (3 * A_STG + (s) * B_STG)
#define SM_TOTAL   (3 * A_STG + 3 * B_STG)   // 81408 B

template <bool RELU, bool ROUND>
__global__ __launch_bounds__(256, 1)
void tgemm64(const float* __restrict__ A,
             const float* __restrict__ Bm,
             const float* __restrict__ bias,
             float* __restrict__ C,
             int nkt,                 // K / BK
             long lda, long ldb, long ldc,
             long strideAe, long strideBe, long strideBiasE, long strideCe)
{
    extern __shared__ char smem[];
    const uint32_t sb = smem_u32(smem);
    const int tid = threadIdx.x;
    const int e   = blockIdx.z;

    A    += (long)e * strideAe + (long)blockIdx.x * 128 * lda;
    Bm   += (long)e * strideBe + (long)blockIdx.y * 256;
    bias += (long)e * strideBiasE + (long)blockIdx.y * 256;
    C    += (long)e * strideCe + (long)blockIdx.x * 128 * ldc + (long)blockIdx.y * 256;

    // warp/lane mapping
    const int w    = tid >> 5;
    const int wm   = w & 1;            // 2 warps in M (64 rows each)
    const int wn   = w >> 1;           // 4 warps in N (64 cols each)
    const int lane = tid & 31;
    const int qr   = lane >> 2;        // 0..7
    const int qc   = lane & 3;         // 0..3

    // staging chunk coords (computed once)
    const int am = tid >> 2;           // A: rows 0..63 (+64 at r=1)
    const int ak = (tid & 3) << 2;     // A: k word 0,4,8,12
    const int bk = tid >> 6;           // B: k rows 0..3 (+4,+8,+12)
    const int bn = (tid & 63) << 2;    // B: n word 0..252

    float acc[4][8][4];
    #pragma unroll
    for (int i = 0; i < 4; i++)
        #pragma unroll
        for (int j = 0; j < 8; j++)
            #pragma unroll
            for (int r = 0; r < 4; r++) acc[i][j][r] = 0.0f;

    // --- staging issue (one stage = 2 A chunks + 4 B chunks per thread) ---
    auto issue = [&](int kt, int s) {
        const long ko = (long)kt * BK;
        {
            const uint32_t d0 = sb + SA_OFF(s);
            cp_async16(d0 + (uint32_t)(am * AP + ak) * 4,        A + (long)am * lda + ko + ak);
            cp_async16(d0 + (uint32_t)((am + 64) * AP + ak) * 4, A + (long)(am + 64) * lda + ko + ak);
        }
        {
            const uint32_t d0 = sb + SB_OFF(s);
            #pragma unroll
            for (int r = 0; r < 4; r++) {
                const int k = bk + r * 4;
                cp_async16(d0 + (uint32_t)(k * BP + bn) * 4, Bm + (ko + k) * ldb + bn);
            }
        }
    };

    // prologue: stages 0,1
    issue(0, 0); CP_COMMIT();
    issue(1, 1); CP_COMMIT();
    CP_WAIT(1);
    __syncthreads();

    for (int kt = 0; kt < nkt; kt++) {
        const int buf = kt % 3;
        const uint32_t* uA = (const uint32_t*)(smem + SA_OFF(buf));
        const uint32_t* uB = (const uint32_t*)(smem + SB_OFF(buf));

        #pragma unroll
        for (int ks = 0; ks < BK; ks += 8) {
            uint32_t aF[4][4];
            uint32_t bF[8][2];
            #pragma unroll
            for (int i = 0; i < 4; i++) {
                const int mtb = wm * 64 + i * 16;
                aF[i][0] = uA[(mtb + qr)     * AP + ks + qc];
                aF[i][1] = uA[(mtb + qr + 8) * AP + ks + qc];
                aF[i][2] = uA[(mtb + qr)     * AP + ks + qc + 4];
                aF[i][3] = uA[(mtb + qr + 8) * AP + ks + qc + 4];
            }
            #pragma unroll
            for (int j = 0; j < 8; j++) {
                const int ntb = wn * 64 + j * 8;
                bF[j][0] = uB[(ks + qc)     * BP + ntb + qr];
                bF[j][1] = uB[(ks + qc + 4) * BP + ntb + qr];
            }
            #pragma unroll
            for (int i = 0; i < 4; i++)
                #pragma unroll
                for (int j = 0; j < 8; j++) {
                    asm volatile(
                        "mma.sync.aligned.m16n8k8.row.col.f32.tf32.tf32.f32 "
                        "{%0,%1,%2,%3}, {%4,%5,%6,%7}, {%8,%9}, {%0,%1,%2,%3};\n"
                        : "+f"(acc[i][j][0]), "+f"(acc[i][j][1]),
                          "+f"(acc[i][j][2]), "+f"(acc[i][j][3])
                        : "r"(aF[i][0]), "r"(aF[i][1]), "r"(aF[i][2]), "r"(aF[i][3]),
                          "r"(bF[j][0]), "r"(bF[j][1]));
                }
        }

        if (kt + 2 < nkt) {
            issue(kt + 2, (kt + 2) % 3);
            CP_COMMIT();
            CP_WAIT(1);          // stage kt+1 guaranteed landed
            __syncthreads();
        } else if (kt + 1 < nkt) {
            CP_WAIT(0);          // drain last in-flight stage
            __syncthreads();
        }
    }

    // ---- epilogue: bias + relu (+tf32 round) + store ----
    #pragma unroll
    for (int j = 0; j < 8; j++) {
        const int ncol = wn * 64 + j * 8 + 2 * qc;
        const float2 bj = *(const float2*)(bias + ncol);
        #pragma unroll
        for (int i = 0; i < 4; i++) {
            const long r0 = wm * 64 + i * 16 + qr;
            float2 v0, v1;
            v0.x = acc[i][j][0] + bj.x;  v0.y = acc[i][j][1] + bj.y;
            v1.x = acc[i][j][2] + bj.x;  v1.y = acc[i][j][3] + bj.y;
            if (RELU) {
                v0.x = fmaxf(v0.x, 0.0f); v0.y = fmaxf(v0.y, 0.0f);
                v1.x = fmaxf(v1.x, 0.0f); v1.y = fmaxf(v1.y, 0.0f);
            }
            if (ROUND) {
                v0.x = rna_tf32(v0.x); v0.y = rna_tf32(v0.y);
                v1.x = rna_tf32(v1.x); v1.y = rna_tf32(v1.y);
            }
            *(float2*)(C + r0 * ldc + ncol)       = v0;
            *(float2*)(C + (r0 + 8) * ldc + ncol) = v1;
        }
    }
}

// ---------------------------------------------------------------------------
// Pre-pass: tf32-round a float array (any of x / W1 / W2 / W3), float4-wide.
// ---------------------------------------------------------------------------
__global__ __launch_bounds__(256)
void round_copy_kernel(const float* __restrict__ src, float* __restrict__ dst, long n4)
{
    long i = (long)blockIdx.x * blockDim.x + threadIdx.x;
    if (i < n4) {
        float4 v = ((const float4*)src)[i];
        v.x = rna_tf32(v.x); v.y = rna_tf32(v.y);
        v.z = rna_tf32(v.z); v.w = rna_tf32(v.w);
        ((float4*)dst)[i] = v;
    }
}

// ---------------------------------------------------------------------------
// Gate kernel (fp32, exact): logits = x @ gate_w, softmax over experts,
// store gates as [B][E][T].
// ---------------------------------------------------------------------------
__global__ __launch_bounds__(256)
void gate_kernel(const float* __restrict__ x,
                 const float* __restrict__ gw,
                 float* __restrict__ gates)
{
    __shared__ float xs[8][D_IN];
    __shared__ float gws[64][32];
    __shared__ float lg[8][32];

    const int tid = threadIdx.x;
    const long b0 = (long)blockIdx.x * 8;

    {
        const float4* xg  = (const float4*)(x + b0 * D_IN);
        float4*       xs4 = (float4*)xs;
        #pragma unroll
        for (int i = tid; i < 8 * D_IN / 4; i += 256) xs4[i] = xg[i];
    }

    const int r = tid >> 5;
    const int c = tid & 31;

    float acc = 0.0f;
    for (int kc = 0; kc < D_IN; kc += 64) {
        __syncthreads();
        const float4* gwg = (const float4*)(gw + (long)kc * 32);
        float4*       gs4 = (float4*)gws;
        for (int i = tid; i < 64 * 32 / 4; i += 256) gs4[i] = gwg[i];
        __syncthreads();
        #pragma unroll
        for (int k = 0; k < 64; k++)
            acc = fmaf(xs[r][kc + k], gws[k][c], acc);
    }

    lg[r][c] = acc;
    __syncthreads();

    const int t  = c >> 3;
    const int base = t << 3;
    const int eI = c & 7;
    float mx = -1e30f;
    #pragma unroll
    for (int j = 0; j < 8; j++) mx = fmaxf(mx, lg[r][base + j]);
    float s = 0.0f;
    #pragma unroll
    for (int j = 0; j < 8; j++) s += expf(lg[r][base + j] - mx);
    float gate = expf(acc - mx) / s;

    gates[(b0 + r) * (E_EXP * T_TASK) + eI * T_TASK + t] = gate;
}

// ---------------------------------------------------------------------------
// Combine: out[t][b][d] = sum_e h3[b][e][d] * gates[b][e][t]
// ---------------------------------------------------------------------------
__global__ __launch_bounds__(128)
void combine_kernel(const float* __restrict__ h3,
                    const float* __restrict__ gates,
                    float* __restrict__ out)
{
    const int  tid = threadIdx.x;
    const long b   = (long)blockIdx.x * 2 + (tid >> 6);
    const int  d4  = (tid & 63);

    __shared__ float g[2][E_EXP * T_TASK];
    if (tid < 2 * E_EXP * T_TASK)
        g[tid >> 5][tid & 31] =
            gates[((long)blockIdx.x * 2 + (tid >> 5)) * (E_EXP * T_TASK) + (tid & 31)];
    __syncthreads();

    const int rsel = tid >> 6;
    float4 a0 = {0,0,0,0}, a1 = {0,0,0,0}, a2 = {0,0,0,0}, a3 = {0,0,0,0};
    #pragma unroll
    for (int e = 0; e < E_EXP; e++) {
        float4 v = *(const float4*)(h3 + ((b * E_EXP + e) * H3_SZ) + d4 * 4);
        const float g0 = g[rsel][e * T_TASK + 0];
        const float g1 = g[rsel][e * T_TASK + 1];
        const float g2 = g[rsel][e * T_TASK + 2];
        const float g3 = g[rsel][e * T_TASK + 3];
        a0.x = fmaf(v.x, g0, a0.x); a0.y = fmaf(v.y, g0, a0.y);
        a0.z = fmaf(v.z, g0, a0.z); a0.w = fmaf(v.w, g0, a0.w);
        a1.x = fmaf(v.x, g1, a1.x); a1.y = fmaf(v.y, g1, a1.y);
        a1.z = fmaf(v.z, g1, a1.z); a1.w = fmaf(v.w, g1, a1.w);
        a2.x = fmaf(v.x, g2, a2.x); a2.y = fmaf(v.y, g2, a2.y);
        a2.z = fmaf(v.z, g2, a2.z); a2.w = fmaf(v.w, g2, a2.w);
        a3.x = fmaf(v.x, g3, a3.x); a3.y = fmaf(v.y, g3, a3.y);
        a3.z = fmaf(v.z, g3, a3.z); a3.w = fmaf(v.w, g3, a3.w);
    }
    const long base = b * H3_SZ + d4 * 4;
    const long ts   = (long)B_SZ * H3_SZ;
    *(float4*)(out + 0 * ts + base) = a0;
    *(float4*)(out + 1 * ts + base) = a1;
    *(float4*)(out + 2 * ts + base) = a2;
    *(float4*)(out + 3 * ts + base) = a3;
}

// ---------------------------------------------------------------------------
extern "C" void kernel_launch(void* const* d_in, const int* in_sizes, int n_in,
                              void* d_out, int out_size)
{
    const float* x      = (const float*)d_in[0];
    const float* W1     = (const float*)d_in[1];
    const float* b1     = (const float*)d_in[2];
    const float* W2     = (const float*)d_in[3];
    const float* b2     = (const float*)d_in[4];
    const float* W3     = (const float*)d_in[5];
    const float* b3     = (const float*)d_in[6];
    const float* gate_w = (const float*)d_in[7];
    float* out = (float*)d_out;

    float *h1, *h2, *h3, *gates, *xr, *w1r, *w2r, *w3r;
    cudaGetSymbolAddress((void**)&h1,    g_h1);
    cudaGetSymbolAddress((void**)&h2,    g_h2);
    cudaGetSymbolAddress((void**)&h3,    g_h3);
    cudaGetSymbolAddress((void**)&gates, g_gates);
    cudaGetSymbolAddress((void**)&xr,    g_xr);
    cudaGetSymbolAddress((void**)&w1r,   g_w1r);
    cudaGetSymbolAddress((void**)&w2r,   g_w2r);
    cudaGetSymbolAddress((void**)&w3r,   g_w3r);

    cudaFuncSetAttribute(tgemm64<true, true>,
                         cudaFuncAttributeMaxDynamicSharedMemorySize, SM_TOTAL);
    cudaFuncSetAttribute(tgemm64<true, false>,
                         cudaFuncAttributeMaxDynamicSharedMemorySize, SM_TOTAL);

    // Pre-pass: tf32-round x and weights (raw-byte cp.async staging requires it)
    {
        long n;
        n = (long)B_SZ * D_IN / 4;
        round_copy_kernel<<<(n + 255) / 256, 256>>>(x, xr, n);
        n = (long)E_EXP * D_IN * H1_SZ / 4;
        round_copy_kernel<<<(n + 255) / 256, 256>>>(W1, w1r, n);
        n = (long)E_EXP * H1_SZ * H2_SZ / 4;
        round_copy_kernel<<<(n + 255) / 256, 256>>>(W2, w2r, n);
        n = (long)E_EXP * H2_SZ * H3_SZ / 4;
        round_copy_kernel<<<(n + 255) / 256, 256>>>(W3, w3r, n);
    }

    // Gates (fp32, reads original x)
    gate_kernel<<<B_SZ / 8, 256>>>(x, gate_w, gates);

    // Layer 1: h1 = round(relu(xr @ W1 + b1))
    {
        dim3 grid(B_SZ / 128, H1_SZ / 256, E_EXP);
        tgemm64<true, true><<<grid, 256, SM_TOTAL>>>(
            xr, w1r, b1, h1, D_IN / BK,
            /*lda*/ D_IN, /*ldb*/ H1_SZ, /*ldc*/ (long)E_EXP * H1_SZ,
            /*strideAe*/ 0, /*strideBe*/ (long)D_IN * H1_SZ,
            /*strideBiasE*/ H1_SZ, /*strideCe*/ H1_SZ);
    }

    // Layer 2: h2 = round(relu(h1 @ W2 + b2))
    {
        dim3 grid(B_SZ / 128, H2_SZ / 256, E_EXP);
        tgemm64<true, true><<<grid, 256, SM_TOTAL>>>(
            h1, w2r, b2, h2, H1_SZ / BK,
            /*lda*/ (long)E_EXP * H1_SZ, /*ldb*/ H2_SZ, /*ldc*/ (long)E_EXP * H2_SZ,
            /*strideAe*/ H1_SZ, /*strideBe*/ (long)H1_SZ * H2_SZ,
            /*strideBiasE*/ H2_SZ, /*strideCe*/ H2_SZ);
    }

    // Layer 3: h3 = relu(h2 @ W3 + b3)
    {
        dim3 grid(B_SZ / 128, H3_SZ / 256, E_EXP);
        tgemm64<true, false><<<grid, 256, SM_TOTAL>>>(
            h2, w3r, b3, h3, H2_SZ / BK,
            /*lda*/ (long)E_EXP * H2_SZ, /*ldb*/ H3_SZ, /*ldc*/ (long)E_EXP * H3_SZ,
            /*strideAe*/ H2_SZ, /*strideBe*/ (long)H2_SZ * H3_SZ,
            /*strideBiasE*/ H3_SZ, /*strideCe*/ H3_SZ);
    }

    // Combine with gates
    combine_kernel<<<B_SZ / 2, 128>>>(h3, gates, out);
}

// round 10
// speedup vs baseline: 3.2299x; 1.0115x over previous
#include <cuda_runtime.h>
#include <cuda_bf16.h>
#include <math.h>
#include <stdint.h>

// Problem constants
#define B_SZ   8192
#define D_IN   1024
#define E_EXP  8
#define T_TASK 4
#define H1_SZ  1024
#define H2_SZ  512
#define H3_SZ  256

// Scratch (device globals: allocation-free, graph-capture safe)
static __device__ float g_h1[(long)B_SZ * E_EXP * H1_SZ];       // 256 MB
static __device__ float g_h2[(long)B_SZ * E_EXP * H2_SZ];       // 128 MB
static __device__ float g_h3[(long)B_SZ * E_EXP * H3_SZ];       //  64 MB
static __device__ float g_gates[(long)B_SZ * E_EXP * T_TASK];   //   1 MB
static __device__ float g_xr [(long)B_SZ * D_IN];               //  32 MB  x  (tf32-rounded)
static __device__ float g_w1r[(long)E_EXP * D_IN * H1_SZ];      //  32 MB  W1 (tf32-rounded)
static __device__ float g_w2r[(long)E_EXP * H1_SZ * H2_SZ];     //  16 MB  W2 (tf32-rounded)
static __device__ float g_w3r[(long)E_EXP * H2_SZ * H3_SZ];     //   4 MB  W3 (tf32-rounded)

__device__ __forceinline__ float rna_tf32(float x) {
    uint32_t r;
    asm("cvt.rna.tf32.f32 %0, %1;" : "=r"(r) : "f"(x));
    return __uint_as_float(r);
}

__device__ __forceinline__ uint32_t smem_u32(const void* p) {
    uint32_t a;
    asm("{ .reg .u64 t; cvta.to.shared.u64 t, %1; cvt.u32.u64 %0, t; }" : "=r"(a) : "l"(p));
    return a;
}

__device__ __forceinline__ void cp_async16(uint32_t dst, const void* src) {
    asm volatile("cp.async.cg.shared.global [%0], [%1], 16;"
                 :: "r"(dst), "l"(src) : "memory");
}
#define CP_COMMIT()  asm volatile("cp.async.commit_group;" ::: "memory")
#define CP_WAIT(n)   asm volatile("cp.async.wait_group %0;" :: "n"(n) : "memory")

// ---------------------------------------------------------------------------
// TF32 mma.sync GEMM: C[e][m][n] = act( sum_k A[e][m][k]*B[e][k][n] + bias[e][n] )
// Block tile 128(M) x 256(N), BK=16, 256 threads = 8 warps (2x4), warp 64x64.
// 4-stage cp.async.cg pipeline (L1-bypass staging). All operands must be
// tf32-exact in GMEM (raw-byte staging).
// Smem: As[m][20] (conflict-free frags: (20*qr+qc)%32 distinct)
//       Bs[k][264] (264%32==8 -> (8*qc+qr)%32 distinct)
// Inner loop: ALL 64 fragment registers hoisted before the mma block so the
// 29-cyc LDS latency is covered by MLP, not by (scarce) cross-warp slack.
// ---------------------------------------------------------------------------
#define BK     16
#define AP     20           // As row stride (words)
#define BP     264          // Bs row stride (words)
#define NSTG   4
#define A_STG  (128 * AP * 4)       // 10240 B per stage
#define B_STG  (BK * BP * 4)        // 16896 B per stage
#define SA_OFF(s)  ((s) * A_STG)
#define SB_OFF(s)  (NSTG * A_STG + (s) * B_STG)
#define SM_TOTAL   (NSTG * A_STG + NSTG * B_STG)   // 108544 B

template <bool RELU, bool ROUND>
__global__ __launch_bounds__(256, 1)
void tgemm64(const float* __restrict__ A,
             const float* __restrict__ Bm,
             const float* __restrict__ bias,
             float* __restrict__ C,
             int nkt,                 // K / BK  (>= 4)
             long lda, long ldb, long ldc,
             long strideAe, long strideBe, long strideBiasE, long strideCe)
{
    extern __shared__ char smem[];
    const uint32_t sb = smem_u32(smem);
    const int tid = threadIdx.x;
    const int e   = blockIdx.z;

    A    += (long)e * strideAe + (long)blockIdx.x * 128 * lda;
    Bm   += (long)e * strideBe + (long)blockIdx.y * 256;
    bias += (long)e * strideBiasE + (long)blockIdx.y * 256;
    C    += (long)e * strideCe + (long)blockIdx.x * 128 * ldc + (long)blockIdx.y * 256;

    // warp/lane mapping
    const int w    = tid >> 5;
    const int wm   = w & 1;            // 2 warps in M (64 rows each)
    const int wn   = w >> 1;           // 4 warps in N (64 cols each)
    const int lane = tid & 31;
    const int qr   = lane >> 2;        // 0..7
    const int qc   = lane & 3;         // 0..3

    // staging chunk coords
    const int am = tid >> 2;           // A: rows 0..63 (+64)
    const int ak = (tid & 3) << 2;     // A: k word 0,4,8,12
    const int bk = tid >> 6;           // B: k rows 0..3 (+4,+8,+12)
    const int bn = (tid & 63) << 2;    // B: n word 0..252

    float acc[4][8][4];
    #pragma unroll
    for (int i = 0; i < 4; i++)
        #pragma unroll
        for (int j = 0; j < 8; j++)
            #pragma unroll
            for (int r = 0; r < 4; r++) acc[i][j][r] = 0.0f;

    auto issue = [&](int kt, int s) {
        const long ko = (long)kt * BK;
        {
            const uint32_t d0 = sb + SA_OFF(s);
            cp_async16(d0 + (uint32_t)(am * AP + ak) * 4,        A + (long)am * lda + ko + ak);
            cp_async16(d0 + (uint32_t)((am + 64) * AP + ak) * 4, A + (long)(am + 64) * lda + ko + ak);
        }
        {
            const uint32_t d0 = sb + SB_OFF(s);
            #pragma unroll
            for (int r = 0; r < 4; r++) {
                const int k = bk + r * 4;
                cp_async16(d0 + (uint32_t)(k * BP + bn) * 4, Bm + (ko + k) * ldb + bn);
            }
        }
    };

    // prologue: stages 0..2 in flight
    issue(0, 0); CP_COMMIT();
    issue(1, 1); CP_COMMIT();
    issue(2, 2); CP_COMMIT();
    CP_WAIT(2);               // stage 0 landed
    __syncthreads();

    for (int kt = 0; kt < nkt; kt++) {
        const int buf = kt & (NSTG - 1);
        const uint32_t* uA = (const uint32_t*)(smem + SA_OFF(buf));
        const uint32_t* uB = (const uint32_t*)(smem + SB_OFF(buf));

        // ---- hoist ALL fragments for this k-tile (64 independent LDS) ----
        uint32_t aF[2][4][4];
        uint32_t bF[2][8][2];
        #pragma unroll
        for (int h = 0; h < 2; h++) {
            const int ks = h * 8;
            #pragma unroll
            for (int i = 0; i < 4; i++) {
                const int mtb = wm * 64 + i * 16;
                aF[h][i][0] = uA[(mtb + qr)     * AP + ks + qc];
                aF[h][i][1] = uA[(mtb + qr + 8) * AP + ks + qc];
                aF[h][i][2] = uA[(mtb + qr)     * AP + ks + qc + 4];
                aF[h][i][3] = uA[(mtb + qr + 8) * AP + ks + qc + 4];
            }
            #pragma unroll
            for (int j = 0; j < 8; j++) {
                const int ntb = wn * 64 + j * 8;
                bF[h][j][0] = uB[(ks + qc)     * BP + ntb + qr];
                bF[h][j][1] = uB[(ks + qc + 4) * BP + ntb + qr];
            }
        }

        // ---- 64 dependency-free mmas ----
        #pragma unroll
        for (int h = 0; h < 2; h++)
            #pragma unroll
            for (int i = 0; i < 4; i++)
                #pragma unroll
                for (int j = 0; j < 8; j++) {
                    asm volatile(
                        "mma.sync.aligned.m16n8k8.row.col.f32.tf32.tf32.f32 "
                        "{%0,%1,%2,%3}, {%4,%5,%6,%7}, {%8,%9}, {%0,%1,%2,%3};\n"
                        : "+f"(acc[i][j][0]), "+f"(acc[i][j][1]),
                          "+f"(acc[i][j][2]), "+f"(acc[i][j][3])
                        : "r"(aF[h][i][0]), "r"(aF[h][i][1]),
                          "r"(aF[h][i][2]), "r"(aF[h][i][3]),
                          "r"(bF[h][j][0]), "r"(bF[h][j][1]));
                }

        // ---- staging for kt+3; empty commit keeps group accounting exact ----
        if (kt + 3 < nkt) issue(kt + 3, (kt + 3) & (NSTG - 1));
        CP_COMMIT();
        CP_WAIT(2);          // stage kt+1 guaranteed landed
        __syncthreads();
    }

    // ---- epilogue: bias + relu (+tf32 round) + store ----
    #pragma unroll
    for (int j = 0; j < 8; j++) {
        const int ncol = wn * 64 + j * 8 + 2 * qc;
        const float2 bj = *(const float2*)(bias + ncol);
        #pragma unroll
        for (int i = 0; i < 4; i++) {
            const long r0 = wm * 64 + i * 16 + qr;
            float2 v0, v1;
            v0.x = acc[i][j][0] + bj.x;  v0.y = acc[i][j][1] + bj.y;
            v1.x = acc[i][j][2] + bj.x;  v1.y = acc[i][j][3] + bj.y;
            if (RELU) {
                v0.x = fmaxf(v0.x, 0.0f); v0.y = fmaxf(v0.y, 0.0f);
                v1.x = fmaxf(v1.x, 0.0f); v1.y = fmaxf(v1.y, 0.0f);
            }
            if (ROUND) {
                v0.x = rna_tf32(v0.x); v0.y = rna_tf32(v0.y);
                v1.x = rna_tf32(v1.x); v1.y = rna_tf32(v1.y);
            }
            *(float2*)(C + r0 * ldc + ncol)       = v0;
            *(float2*)(C + (r0 + 8) * ldc + ncol) = v1;
        }
    }
}

// ---------------------------------------------------------------------------
// Pre-pass: tf32-round a float array, float4-wide.
// ---------------------------------------------------------------------------
__global__ __launch_bounds__(256)
void round_copy_kernel(const float* __restrict__ src, float* __restrict__ dst, long n4)
{
    long i = (long)blockIdx.x * blockDim.x + threadIdx.x;
    if (i < n4) {
        float4 v = ((const float4*)src)[i];
        v.x = rna_tf32(v.x); v.y = rna_tf32(v.y);
        v.z = rna_tf32(v.z); v.w = rna_tf32(v.w);
        ((float4*)dst)[i] = v;
    }
}

// ---------------------------------------------------------------------------
// Gate kernel (fp32, exact): logits = x @ gate_w, softmax over experts,
// store gates as [B][E][T].
// ---------------------------------------------------------------------------
__global__ __launch_bounds__(256)
void gate_kernel(const float* __restrict__ x,
                 const float* __restrict__ gw,
                 float* __restrict__ gates)
{
    __shared__ float xs[8][D_IN];
    __shared__ float gws[64][32];
    __shared__ float lg[8][32];

    const int tid = threadIdx.x;
    const long b0 = (long)blockIdx.x * 8;

    {
        const float4* xg  = (const float4*)(x + b0 * D_IN);
        float4*       xs4 = (float4*)xs;
        #pragma unroll
        for (int i = tid; i < 8 * D_IN / 4; i += 256) xs4[i] = xg[i];
    }

    const int r = tid >> 5;
    const int c = tid & 31;

    float acc = 0.0f;
    for (int kc = 0; kc < D_IN; kc += 64) {
        __syncthreads();
        const float4* gwg = (const float4*)(gw + (long)kc * 32);
        float4*       gs4 = (float4*)gws;
        for (int i = tid; i < 64 * 32 / 4; i += 256) gs4[i] = gwg[i];
        __syncthreads();
        #pragma unroll
        for (int k = 0; k < 64; k++)
            acc = fmaf(xs[r][kc + k], gws[k][c], acc);
    }

    lg[r][c] = acc;
    __syncthreads();

    const int t  = c >> 3;
    const int base = t << 3;
    const int eI = c & 7;
    float mx = -1e30f;
    #pragma unroll
    for (int j = 0; j < 8; j++) mx = fmaxf(mx, lg[r][base + j]);
    float s = 0.0f;
    #pragma unroll
    for (int j = 0; j < 8; j++) s += expf(lg[r][base + j] - mx);
    float gate = expf(acc - mx) / s;

    gates[(b0 + r) * (E_EXP * T_TASK) + eI * T_TASK + t] = gate;
}

// ---------------------------------------------------------------------------
// Combine: out[t][b][d] = sum_e h3[b][e][d] * gates[b][e][t]
// ---------------------------------------------------------------------------
__global__ __launch_bounds__(128)
void combine_kernel(const float* __restrict__ h3,
                    const float* __restrict__ gates,
                    float* __restrict__ out)
{
    const int  tid = threadIdx.x;
    const long b   = (long)blockIdx.x * 2 + (tid >> 6);
    const int  d4  = (tid & 63);

    __shared__ float g[2][E_EXP * T_TASK];
    if (tid < 2 * E_EXP * T_TASK)
        g[tid >> 5][tid & 31] =
            gates[((long)blockIdx.x * 2 + (tid >> 5)) * (E_EXP * T_TASK) + (tid & 31)];
    __syncthreads();

    const int rsel = tid >> 6;
    float4 a0 = {0,0,0,0}, a1 = {0,0,0,0}, a2 = {0,0,0,0}, a3 = {0,0,0,0};
    #pragma unroll
    for (int e = 0; e < E_EXP; e++) {
        float4 v = *(const float4*)(h3 + ((b * E_EXP + e) * H3_SZ) + d4 * 4);
        const float g0 = g[rsel][e * T_TASK + 0];
        const float g1 = g[rsel][e * T_TASK + 1];
        const float g2 = g[rsel][e * T_TASK + 2];
        const float g3 = g[rsel][e * T_TASK + 3];
        a0.x = fmaf(v.x, g0, a0.x); a0.y = fmaf(v.y, g0, a0.y);
        a0.z = fmaf(v.z, g0, a0.z); a0.w = fmaf(v.w, g0, a0.w);
        a1.x = fmaf(v.x, g1, a1.x); a1.y = fmaf(v.y, g1, a1.y);
        a1.z = fmaf(v.z, g1, a1.z); a1.w = fmaf(v.w, g1, a1.w);
        a2.x = fmaf(v.x, g2, a2.x); a2.y = fmaf(v.y, g2, a2.y);
        a2.z = fmaf(v.z, g2, a2.z); a2.w = fmaf(v.w, g2, a2.w);
        a3.x = fmaf(v.x, g3, a3.x); a3.y = fmaf(v.y, g3, a3.y);
        a3.z = fmaf(v.z, g3, a3.z); a3.w = fmaf(v.w, g3, a3.w);
    }
    const long base = b * H3_SZ + d4 * 4;
    const long ts   = (long)B_SZ * H3_SZ;
    *(float4*)(out + 0 * ts + base) = a0;
    *(float4*)(out + 1 * ts + base) = a1;
    *(float4*)(out + 2 * ts + base) = a2;
    *(float4*)(out + 3 * ts + base) = a3;
}

// ---------------------------------------------------------------------------
extern "C" void kernel_launch(void* const* d_in, const int* in_sizes, int n_in,
                              void* d_out, int out_size)
{
    const float* x      = (const float*)d_in[0];
    const float* W1     = (const float*)d_in[1];
    const float* b1     = (const float*)d_in[2];
    const float* W2     = (const float*)d_in[3];
    const float* b2     = (const float*)d_in[4];
    const float* W3     = (const float*)d_in[5];
    const float* b3     = (const float*)d_in[6];
    const float* gate_w = (const float*)d_in[7];
    float* out = (float*)d_out;

    float *h1, *h2, *h3, *gates, *xr, *w1r, *w2r, *w3r;
    cudaGetSymbolAddress((void**)&h1,    g_h1);
    cudaGetSymbolAddress((void**)&h2,    g_h2);
    cudaGetSymbolAddress((void**)&h3,    g_h3);
    cudaGetSymbolAddress((void**)&gates, g_gates);
    cudaGetSymbolAddress((void**)&xr,    g_xr);
    cudaGetSymbolAddress((void**)&w1r,   g_w1r);
    cudaGetSymbolAddress((void**)&w2r,   g_w2r);
    cudaGetSymbolAddress((void**)&w3r,   g_w3r);

    cudaFuncSetAttribute(tgemm64<true, true>,
                         cudaFuncAttributeMaxDynamicSharedMemorySize, SM_TOTAL);
    cudaFuncSetAttribute(tgemm64<true, false>,
                         cudaFuncAttributeMaxDynamicSharedMemorySize, SM_TOTAL);

    // Pre-pass: tf32-round x and weights (raw-byte cp.async staging requires it)
    {
        long n;
        n = (long)B_SZ * D_IN / 4;
        round_copy_kernel<<<(n + 255) / 256, 256>>>(x, xr, n);
        n = (long)E_EXP * D_IN * H1_SZ / 4;
        round_copy_kernel<<<(n + 255) / 256, 256>>>(W1, w1r, n);
        n = (long)E_EXP * H1_SZ * H2_SZ / 4;
        round_copy_kernel<<<(n + 255) / 256, 256>>>(W2, w2r, n);
        n = (long)E_EXP * H2_SZ * H3_SZ / 4;
        round_copy_kernel<<<(n + 255) / 256, 256>>>(W3, w3r, n);
    }

    // Gates (fp32, reads original x)
    gate_kernel<<<B_SZ / 8, 256>>>(x, gate_w, gates);

    // Layer 1: h1 = round(relu(xr @ W1 + b1))
    {
        dim3 grid(B_SZ / 128, H1_SZ / 256, E_EXP);
        tgemm64<true, true><<<grid, 256, SM_TOTAL>>>(
            xr, w1r, b1, h1, D_IN / BK,
            /*lda*/ D_IN, /*ldb*/ H1_SZ, /*ldc*/ (long)E_EXP * H1_SZ,
            /*strideAe*/ 0, /*strideBe*/ (long)D_IN * H1_SZ,
            /*strideBiasE*/ H1_SZ, /*strideCe*/ H1_SZ);
    }

    // Layer 2: h2 = round(relu(h1 @ W2 + b2))
    {
        dim3 grid(B_SZ / 128, H2_SZ / 256, E_EXP);
        tgemm64<true, true><<<grid, 256, SM_TOTAL>>>(
            h1, w2r, b2, h2, H1_SZ / BK,
            /*lda*/ (long)E_EXP * H1_SZ, /*ldb*/ H2_SZ, /*ldc*/ (long)E_EXP * H2_SZ,
            /*strideAe*/ H1_SZ, /*strideBe*/ (long)H1_SZ * H2_SZ,
            /*strideBiasE*/ H2_SZ, /*strideCe*/ H2_SZ);
    }

    // Layer 3: h3 = relu(h2 @ W3 + b3)
    {
        dim3 grid(B_SZ / 128, H3_SZ / 256, E_EXP);
        tgemm64<true, false><<<grid, 256, SM_TOTAL>>>(
            h2, w3r, b3, h3, H2_SZ / BK,
            /*lda*/ (long)E_EXP * H2_SZ, /*ldb*/ H3_SZ, /*ldc*/ (long)E_EXP * H3_SZ,
            /*strideAe*/ H2_SZ, /*strideBe*/ (long)H2_SZ * H3_SZ,
            /*strideBiasE*/ H3_SZ, /*strideCe*/ H3_SZ);
    }

    // Combine with gates
    combine_kernel<<<B_SZ / 2, 128>>>(h3, gates, out);
}

// round 14
// speedup vs baseline: 4.0936x; 1.2674x over previous
#include <cuda_runtime.h>
#include <cuda_bf16.h>
#include <math.h>
#include <stdint.h>

// Problem constants
#define B_SZ   8192
#define D_IN   1024
#define E_EXP  8
#define T_TASK 4
#define H1_SZ  1024
#define H2_SZ  512
#define H3_SZ  256

// Scratch (device globals: allocation-free, graph-capture safe)
static __device__ float g_h1[(long)B_SZ * E_EXP * H1_SZ];       // 256 MB
static __device__ float g_h2[(long)B_SZ * E_EXP * H2_SZ];       // 128 MB
static __device__ float g_h3[(long)B_SZ * E_EXP * H3_SZ];       //  64 MB
static __device__ float g_gates[(long)B_SZ * E_EXP * T_TASK];   //   1 MB
static __device__ float g_xr [(long)B_SZ * D_IN];               //  32 MB  x  (tf32-rounded)
static __device__ float g_w1r[(long)E_EXP * D_IN * H1_SZ];      //  32 MB  W1 (tf32-rounded)
static __device__ float g_w2r[(long)E_EXP * H1_SZ * H2_SZ];     //  16 MB  W2 (tf32-rounded)
static __device__ float g_w3r[(long)E_EXP * H2_SZ * H3_SZ];     //   4 MB  W3 (tf32-rounded)

__device__ __forceinline__ float rna_tf32(float x) {
    uint32_t r;
    asm("cvt.rna.tf32.f32 %0, %1;" : "=r"(r) : "f"(x));
    return __uint_as_float(r);
}

__device__ __forceinline__ uint32_t smem_u32(const void* p) {
    uint32_t a;
    asm("{ .reg .u64 t; cvta.to.shared.u64 t, %1; cvt.u32.u64 %0, t; }" : "=r"(a) : "l"(p));
    return a;
}

__device__ __forceinline__ void cp_async16(uint32_t dst, const void* src) {
    asm volatile("cp.async.cg.shared.global [%0], [%1], 16;"
                 :: "r"(dst), "l"(src) : "memory");
}
#define CP_COMMIT()  asm volatile("cp.async.commit_group;" ::: "memory")
#define CP_WAIT(n)   asm volatile("cp.async.wait_group %0;" :: "n"(n) : "memory")

// ---------------------------------------------------------------------------
// TF32 mma.sync GEMM: C[e][m][n] = act( sum_k A[e][m][k]*B[e][k][n] + bias[e][n] )
// Block tile 128(M) x 256(N), BK=16, 256 threads = 8 warps (2x4), warp 64x64.
// 4-stage cp.async.cg pipeline. All operands must be tf32-exact in GMEM.
// Smem: As[m][20], Bs[k][264] (both conflict-free for fragment loads).
// Inner loop: cross-half fragment DOUBLE-BUFFER — prefetch the NEXT k8-half's
// fragments while the CURRENT half's mmas issue, so LDS rides the mma-throttle
// shadow and the tensor pipe never waits on shared memory.
// ---------------------------------------------------------------------------
#define BK     16
#define AP     20           // As row stride (words)
#define BP     264          // Bs row stride (words)
#define NSTG   4
#define A_STG  (128 * AP * 4)       // 10240 B per stage
#define B_STG  (BK * BP * 4)        // 16896 B per stage
#define SA_OFF(s)  ((s) * A_STG)
#define SB_OFF(s)  (NSTG * A_STG + (s) * B_STG)
#define SM_TOTAL   (NSTG * A_STG + NSTG * B_STG)   // 108544 B

template <bool RELU, bool ROUND>
__global__ __launch_bounds__(256, 1)
void tgemm64(const float* __restrict__ A,
             const float* __restrict__ Bm,
             const float* __restrict__ bias,
             float* __restrict__ C,
             int nkt,                 // K / BK  (>= 4)
             long lda, long ldb, long ldc,
             long strideAe, long strideBe, long strideBiasE, long strideCe)
{
    extern __shared__ char smem[];
    const uint32_t sb = smem_u32(smem);
    const int tid = threadIdx.x;
    const int e   = blockIdx.z;

    A    += (long)e * strideAe + (long)blockIdx.x * 128 * lda;
    Bm   += (long)e * strideBe + (long)blockIdx.y * 256;
    bias += (long)e * strideBiasE + (long)blockIdx.y * 256;
    C    += (long)e * strideCe + (long)blockIdx.x * 128 * ldc + (long)blockIdx.y * 256;

    // warp/lane mapping
    const int w    = tid >> 5;
    const int wm   = w & 1;            // 2 warps in M (64 rows each)
    const int wn   = w >> 1;           // 4 warps in N (64 cols each)
    const int lane = tid & 31;
    const int qr   = lane >> 2;        // 0..7
    const int qc   = lane & 3;         // 0..3

    // staging chunk coords
    const int am = tid >> 2;           // A: rows 0..63 (+64)
    const int ak = (tid & 3) << 2;     // A: k word 0,4,8,12
    const int bk = tid >> 6;           // B: k rows 0..3 (+4,+8,+12)
    const int bn = (tid & 63) << 2;    // B: n word 0..252

    // fragment smem word-offsets (precomputed once, add stage base)
    const int mtb0 = wm * 64;
    const int ntb0 = wn * 64;

    float acc[4][8][4];
    #pragma unroll
    for (int i = 0; i < 4; i++)
        #pragma unroll
        for (int j = 0; j < 8; j++)
            #pragma unroll
            for (int r = 0; r < 4; r++) acc[i][j][r] = 0.0f;

    auto issue = [&](int kt, int s) {
        const long ko = (long)kt * BK;
        {
            const uint32_t d0 = sb + SA_OFF(s);
            cp_async16(d0 + (uint32_t)(am * AP + ak) * 4,        A + (long)am * lda + ko + ak);
            cp_async16(d0 + (uint32_t)((am + 64) * AP + ak) * 4, A + (long)(am + 64) * lda + ko + ak);
        }
        {
            const uint32_t d0 = sb + SB_OFF(s);
            #pragma unroll
            for (int r = 0; r < 4; r++) {
                const int k = bk + r * 4;
                cp_async16(d0 + (uint32_t)(k * BP + bn) * 4, Bm + (ko + k) * ldb + bn);
            }
        }
    };

    // load one k8-half's fragments from stage s at k-offset ks
    auto load_half = [&](int s, int ks, uint32_t aF[4][4], uint32_t bF[8][2]) {
        const uint32_t* uA = (const uint32_t*)(smem + SA_OFF(s));
        const uint32_t* uB = (const uint32_t*)(smem + SB_OFF(s));
        #pragma unroll
        for (int i = 0; i < 4; i++) {
            const int mtb = mtb0 + i * 16;
            aF[i][0] = uA[(mtb + qr)     * AP + ks + qc];
            aF[i][1] = uA[(mtb + qr + 8) * AP + ks + qc];
            aF[i][2] = uA[(mtb + qr)     * AP + ks + qc + 4];
            aF[i][3] = uA[(mtb + qr + 8) * AP + ks + qc + 4];
        }
        #pragma unroll
        for (int j = 0; j < 8; j++) {
            const int ntb = ntb0 + j * 8;
            bF[j][0] = uB[(ks + qc)     * BP + ntb + qr];
            bF[j][1] = uB[(ks + qc + 4) * BP + ntb + qr];
        }
    };

    auto mma_half = [&](const uint32_t aF[4][4], const uint32_t bF[8][2]) {
        #pragma unroll
        for (int i = 0; i < 4; i++)
            #pragma unroll
            for (int j = 0; j < 8; j++) {
                asm volatile(
                    "mma.sync.aligned.m16n8k8.row.col.f32.tf32.tf32.f32 "
                    "{%0,%1,%2,%3}, {%4,%5,%6,%7}, {%8,%9}, {%0,%1,%2,%3};\n"
                    : "+f"(acc[i][j][0]), "+f"(acc[i][j][1]),
                      "+f"(acc[i][j][2]), "+f"(acc[i][j][3])
                    : "r"(aF[i][0]), "r"(aF[i][1]), "r"(aF[i][2]), "r"(aF[i][3]),
                      "r"(bF[j][0]), "r"(bF[j][1]));
            }
    };

    // prologue: stages 0..2 in flight; stages 0 and 1 landed before loop
    issue(0, 0); CP_COMMIT();
    issue(1, 1); CP_COMMIT();
    issue(2, 2); CP_COMMIT();
    CP_WAIT(1);               // stages 0,1 landed
    __syncthreads();

    uint32_t aC[4][4], bC[8][2];   // current half
    uint32_t aN[4][4], bN[8][2];   // next half (prefetch)
    load_half(0, 0, aC, bC);

    for (int kt = 0; kt < nkt; kt++) {
        const int buf  = kt & (NSTG - 1);
        const int nxt  = (kt + 1 < nkt) ? ((kt + 1) & (NSTG - 1)) : 0;

        // h=0: prefetch (kt, h=1) while mma'ing (kt, h=0)
        load_half(buf, 8, aN, bN);
        mma_half(aC, bC);

        // h=1: prefetch (kt+1, h=0) while mma'ing (kt, h=1)
        load_half(nxt, 0, aC, bC);
        mma_half(aN, bN);

        // pipeline maintenance: issue kt+3, confirm stage kt+2 landed
        if (kt + 3 < nkt) issue(kt + 3, (kt + 3) & (NSTG - 1));
        CP_COMMIT();
        CP_WAIT(1);
        __syncthreads();
    }

    // ---- epilogue: bias + relu (+tf32 round) + store ----
    #pragma unroll
    for (int j = 0; j < 8; j++) {
        const int ncol = wn * 64 + j * 8 + 2 * qc;
        const float2 bj = *(const float2*)(bias + ncol);
        #pragma unroll
        for (int i = 0; i < 4; i++) {
            const long r0 = wm * 64 + i * 16 + qr;
            float2 v0, v1;
            v0.x = acc[i][j][0] + bj.x;  v0.y = acc[i][j][1] + bj.y;
            v1.x = acc[i][j][2] + bj.x;  v1.y = acc[i][j][3] + bj.y;
            if (RELU) {
                v0.x = fmaxf(v0.x, 0.0f); v0.y = fmaxf(v0.y, 0.0f);
                v1.x = fmaxf(v1.x, 0.0f); v1.y = fmaxf(v1.y, 0.0f);
            }
            if (ROUND) {
                v0.x = rna_tf32(v0.x); v0.y = rna_tf32(v0.y);
                v1.x = rna_tf32(v1.x); v1.y = rna_tf32(v1.y);
            }
            *(float2*)(C + r0 * ldc + ncol)       = v0;
            *(float2*)(C + (r0 + 8) * ldc + ncol) = v1;
        }
    }
}

// ---------------------------------------------------------------------------
// Pre-pass: tf32-round x, W1, W2, W3 in ONE kernel (segmented grid-stride).
// Element counts in float4 units.
// ---------------------------------------------------------------------------
#define N4_X   ((long)B_SZ * D_IN / 4)                 // 2097152
#define N4_W1  ((long)E_EXP * D_IN * H1_SZ / 4)        // 2097152
#define N4_W2  ((long)E_EXP * H1_SZ * H2_SZ / 4)       // 1048576
#define N4_W3  ((long)E_EXP * H2_SZ * H3_SZ / 4)       //  262144
#define N4_ALL (N4_X + N4_W1 + N4_W2 + N4_W3)          // 5505024

__global__ __launch_bounds__(256)
void round_all_kernel(const float* __restrict__ x,  float* __restrict__ xr,
                      const float* __restrict__ w1, float* __restrict__ w1r,
                      const float* __restrict__ w2, float* __restrict__ w2r,
                      const float* __restrict__ w3, float* __restrict__ w3r)
{
    long i = (long)blockIdx.x * blockDim.x + threadIdx.x;
    if (i >= N4_ALL) return;
    const float4* src;
    float4* dst;
    long off;
    if (i < N4_X)                       { src = (const float4*)x;  dst = (float4*)xr;  off = i; }
    else if (i < N4_X + N4_W1)          { src = (const float4*)w1; dst = (float4*)w1r; off = i - N4_X; }
    else if (i < N4_X + N4_W1 + N4_W2)  { src = (const float4*)w2; dst = (float4*)w2r; off = i - N4_X - N4_W1; }
    else                                { src = (const float4*)w3; dst = (float4*)w3r; off = i - N4_X - N4_W1 - N4_W2; }
    float4 v = src[off];
    v.x = rna_tf32(v.x); v.y = rna_tf32(v.y);
    v.z = rna_tf32(v.z); v.w = rna_tf32(v.w);
    dst[off] = v;
}

// ---------------------------------------------------------------------------
// Gate kernel (fp32, exact): logits = x @ gate_w, softmax over experts,
// store gates as [B][E][T].
// ---------------------------------------------------------------------------
__global__ __launch_bounds__(256)
void gate_kernel(const float* __restrict__ x,
                 const float* __restrict__ gw,
                 float* __restrict__ gates)
{
    __shared__ float xs[8][D_IN];
    __shared__ float gws[64][32];
    __shared__ float lg[8][32];

    const int tid = threadIdx.x;
    const long b0 = (long)blockIdx.x * 8;

    {
        const float4* xg  = (const float4*)(x + b0 * D_IN);
        float4*       xs4 = (float4*)xs;
        #pragma unroll
        for (int i = tid; i < 8 * D_IN / 4; i += 256) xs4[i] = xg[i];
    }

    const int r = tid >> 5;
    const int c = tid & 31;

    float acc = 0.0f;
    for (int kc = 0; kc < D_IN; kc += 64) {
        __syncthreads();
        const float4* gwg = (const float4*)(gw + (long)kc * 32);
        float4*       gs4 = (float4*)gws;
        for (int i = tid; i < 64 * 32 / 4; i += 256) gs4[i] = gwg[i];
        __syncthreads();
        #pragma unroll
        for (int k = 0; k < 64; k++)
            acc = fmaf(xs[r][kc + k], gws[k][c], acc);
    }

    lg[r][c] = acc;
    __syncthreads();

    const int t  = c >> 3;
    const int base = t << 3;
    const int eI = c & 7;
    float mx = -1e30f;
    #pragma unroll
    for (int j = 0; j < 8; j++) mx = fmaxf(mx, lg[r][base + j]);
    float s = 0.0f;
    #pragma unroll
    for (int j = 0; j < 8; j++) s += expf(lg[r][base + j] - mx);
    float gate = expf(acc - mx) / s;

    gates[(b0 + r) * (E_EXP * T_TASK) + eI * T_TASK + t] = gate;
}

// ---------------------------------------------------------------------------
// Combine: out[t][b][d] = sum_e h3[b][e][d] * gates[b][e][t]
// ---------------------------------------------------------------------------
__global__ __launch_bounds__(128)
void combine_kernel(const float* __restrict__ h3,
                    const float* __restrict__ gates,
                    float* __restrict__ out)
{
    const int  tid = threadIdx.x;
    const long b   = (long)blockIdx.x * 2 + (tid >> 6);
    const int  d4  = (tid & 63);

    __shared__ float g[2][E_EXP * T_TASK];
    if (tid < 2 * E_EXP * T_TASK)
        g[tid >> 5][tid & 31] =
            gates[((long)blockIdx.x * 2 + (tid >> 5)) * (E_EXP * T_TASK) + (tid & 31)];
    __syncthreads();

    const int rsel = tid >> 6;
    float4 a0 = {0,0,0,0}, a1 = {0,0,0,0}, a2 = {0,0,0,0}, a3 = {0,0,0,0};
    #pragma unroll
    for (int e = 0; e < E_EXP; e++) {
        float4 v = *(const float4*)(h3 + ((b * E_EXP + e) * H3_SZ) + d4 * 4);
        const float g0 = g[rsel][e * T_TASK + 0];
        const float g1 = g[rsel][e * T_TASK + 1];
        const float g2 = g[rsel][e * T_TASK + 2];
        const float g3 = g[rsel][e * T_TASK + 3];
        a0.x = fmaf(v.x, g0, a0.x); a0.y = fmaf(v.y, g0, a0.y);
        a0.z = fmaf(v.z, g0, a0.z); a0.w = fmaf(v.w, g0, a0.w);
        a1.x = fmaf(v.x, g1, a1.x); a1.y = fmaf(v.y, g1, a1.y);
        a1.z = fmaf(v.z, g1, a1.z); a1.w = fmaf(v.w, g1, a1.w);
        a2.x = fmaf(v.x, g2, a2.x); a2.y = fmaf(v.y, g2, a2.y);
        a2.z = fmaf(v.z, g2, a2.z); a2.w = fmaf(v.w, g2, a2.w);
        a3.x = fmaf(v.x, g3, a3.x); a3.y = fmaf(v.y, g3, a3.y);
        a3.z = fmaf(v.z, g3, a3.z); a3.w = fmaf(v.w, g3, a3.w);
    }
    const long base = b * H3_SZ + d4 * 4;
    const long ts   = (long)B_SZ * H3_SZ;
    *(float4*)(out + 0 * ts + base) = a0;
    *(float4*)(out + 1 * ts + base) = a1;
    *(float4*)(out + 2 * ts + base) = a2;
    *(float4*)(out + 3 * ts + base) = a3;
}

// ---------------------------------------------------------------------------
extern "C" void kernel_launch(void* const* d_in, const int* in_sizes, int n_in,
                              void* d_out, int out_size)
{
    const float* x      = (const float*)d_in[0];
    const float* W1     = (const float*)d_in[1];
    const float* b1     = (const float*)d_in[2];
    const float* W2     = (const float*)d_in[3];
    const float* b2     = (const float*)d_in[4];
    const float* W3     = (const float*)d_in[5];
    const float* b3     = (const float*)d_in[6];
    const float* gate_w = (const float*)d_in[7];
    float* out = (float*)d_out;

    float *h1, *h2, *h3, *gates, *xr, *w1r, *w2r, *w3r;
    cudaGetSymbolAddress((void**)&h1,    g_h1);
    cudaGetSymbolAddress((void**)&h2,    g_h2);
    cudaGetSymbolAddress((void**)&h3,    g_h3);
    cudaGetSymbolAddress((void**)&gates, g_gates);
    cudaGetSymbolAddress((void**)&xr,    g_xr);
    cudaGetSymbolAddress((void**)&w1r,   g_w1r);
    cudaGetSymbolAddress((void**)&w2r,   g_w2r);
    cudaGetSymbolAddress((void**)&w3r,   g_w3r);

    cudaFuncSetAttribute(tgemm64<true, true>,
                         cudaFuncAttributeMaxDynamicSharedMemorySize, SM_TOTAL);
    cudaFuncSetAttribute(tgemm64<true, false>,
                         cudaFuncAttributeMaxDynamicSharedMemorySize, SM_TOTAL);

    // Pre-pass: tf32-round x and all weights in one launch
    round_all_kernel<<<(int)((N4_ALL + 255) / 256), 256>>>(
        x, xr, W1, w1r, W2, w2r, W3, w3r);

    // Gates (fp32, reads original x)
    gate_kernel<<<B_SZ / 8, 256>>>(x, gate_w, gates);

    // Layer 1: h1 = round(relu(xr @ W1 + b1))
    {
        dim3 grid(B_SZ / 128, H1_SZ / 256, E_EXP);
        tgemm64<true, true><<<grid, 256, SM_TOTAL>>>(
            xr, w1r, b1, h1, D_IN / BK,
            /*lda*/ D_IN, /*ldb*/ H1_SZ, /*ldc*/ (long)E_EXP * H1_SZ,
            /*strideAe*/ 0, /*strideBe*/ (long)D_IN * H1_SZ,
            /*strideBiasE*/ H1_SZ, /*strideCe*/ H1_SZ);
    }

    // Layer 2: h2 = round(relu(h1 @ W2 + b2))
    {
        dim3 grid(B_SZ / 128, H2_SZ / 256, E_EXP);
        tgemm64<true, true><<<grid, 256, SM_TOTAL>>>(
            h1, w2r, b2, h2, H1_SZ / BK,
            /*lda*/ (long)E_EXP * H1_SZ, /*ldb*/ H2_SZ, /*ldc*/ (long)E_EXP * H2_SZ,
            /*strideAe*/ H1_SZ, /*strideBe*/ (long)H1_SZ * H2_SZ,
            /*strideBiasE*/ H2_SZ, /*strideCe*/ H2_SZ);
    }

    // Layer 3: h3 = relu(h2 @ W3 + b3)
    {
        dim3 grid(B_SZ / 128, H3_SZ / 256, E_EXP);
        tgemm64<true, false><<<grid, 256, SM_TOTAL>>>(
            h2, w3r, b3, h3, H2_SZ / BK,
            /*lda*/ (long)E_EXP * H2_SZ, /*ldb*/ H3_SZ, /*ldc*/ (long)E_EXP * H3_SZ,
            /*strideAe*/ H2_SZ, /*strideBe*/ (long)H2_SZ * H3_SZ,
            /*strideBiasE*/ H3_SZ, /*strideCe*/ H3_SZ);
    }

    // Combine with gates
    combine_kernel<<<B_SZ / 2, 128>>>(h3, gates, out);
}